// round 2
// baseline (speedup 1.0000x reference)
#include <cuda_runtime.h>

#define MTOT 16384      // B*N = 32*512
#define FEMB 3072
#define FVIS 6
#define FBB  4
#define FKP  51
#define FTOT 3133       // 3072+6+4+51
#define TDIM 256

#define BM 128
#define BN 128
#define BK 16
#define SPAD 132        // BM/BN + 4 pad: keeps float4 LDS 16B-aligned, kills STS conflicts

__device__ int g_count;
__device__ int g_rows[MTOT];

// ---------------------------------------------------------------------------
// Kernel 1: zero the output (poisoned 0xAA by harness) and reset counter
// ---------------------------------------------------------------------------
__global__ void zero_and_reset(float4* __restrict__ out, int n4) {
    if (blockIdx.x == 0 && threadIdx.x == 0) g_count = 0;
    int i = blockIdx.x * blockDim.x + threadIdx.x;
    int stride = gridDim.x * blockDim.x;
    float4 z = make_float4(0.f, 0.f, 0.f, 0.f);
    for (; i < n4; i += stride) out[i] = z;
}

// ---------------------------------------------------------------------------
// Kernel 2: warp-aggregated compaction of active row indices.
// feats_masks is a jnp.bool_ array; the harness materializes it as int32.
// ---------------------------------------------------------------------------
__global__ void compact_rows(const int* __restrict__ mask) {
    int m = blockIdx.x * blockDim.x + threadIdx.x;
    bool act = (m < MTOT) && (mask[m] != 0);
    unsigned bal = __ballot_sync(0xFFFFFFFFu, act);
    int lane = threadIdx.x & 31;
    int base = 0;
    if (lane == 0 && bal) base = atomicAdd(&g_count, __popc(bal));
    base = __shfl_sync(0xFFFFFFFFu, base, 0);
    if (act) {
        int pos = base + __popc(bal & ((1u << lane) - 1u));
        g_rows[pos] = m;
    }
}

// ---------------------------------------------------------------------------
// Concatenated-feature loader (tail region only: f >= 3072)
// ---------------------------------------------------------------------------
__device__ __forceinline__ float load_feat(
    const float* __restrict__ emb, const float* __restrict__ vis,
    const float* __restrict__ bb,  const float* __restrict__ kp,
    int g, int f)
{
    if (f < FEMB)              return emb[(size_t)g * FEMB + f];
    if (f < FEMB + FVIS)       return vis[(size_t)g * FVIS + (f - FEMB)];
    if (f < FEMB + FVIS + FBB) return bb[(size_t)g * FBB + (f - FEMB - FVIS)];
    if (f < FTOT)              return kp[(size_t)g * FKP + (f - FEMB - FVIS - FBB)];
    return 0.f;
}

// ---------------------------------------------------------------------------
// Kernel 3: tiled fp32 GEMM over gathered rows.
// C[g, t] = sum_f A[g,f] * W[t,f] + b[t]   for active rows only.
// ---------------------------------------------------------------------------
__global__ __launch_bounds__(256) void gemm_masked(
    const float* __restrict__ emb, const float* __restrict__ vis,
    const float* __restrict__ bb,  const float* __restrict__ kp,
    const float* __restrict__ W,   const float* __restrict__ bias,
    float* __restrict__ out)
{
    __shared__ float As[BK][SPAD];
    __shared__ float Ws[BK][SPAD];

    const int cnt = g_count;
    const int row0 = blockIdx.x * BM;
    if (row0 >= cnt) return;
    const int col0 = blockIdx.y * BN;

    const int tid = threadIdx.x;
    const int tx = tid & 15;      // 0..15 -> 8 output cols each
    const int ty = tid >> 4;      // 0..15 -> 8 output rows each

    // --- A main-region (embeddings) vector-load lanes: 512 float4/stage ---
    const int r1 = tid >> 2;          // tile rows 0..63
    const int r2 = r1 + 64;           // tile rows 64..127
    const int kq = (tid & 3) * 4;     // k offset within BK: 0,4,8,12
    const int gr1 = g_rows[min(row0 + r1, cnt - 1)];
    const int gr2 = g_rows[min(row0 + r2, cnt - 1)];

    // --- A tail scalar lanes: 128 rows x 16 k, 8 elems/thread ---
    const int r3 = tid >> 1;
    const int k3 = (tid & 1) * 8;
    const int gr3 = g_rows[min(row0 + r3, cnt - 1)];

    // --- W load lanes: coalesced along f ---
    const int wk  = tid & 15;         // k within BK
    const int wc0 = tid >> 4;         // base col, +j*16 for j=0..7

    float acc[8][8];
#pragma unroll
    for (int i = 0; i < 8; i++)
#pragma unroll
        for (int j = 0; j < 8; j++) acc[i][j] = 0.f;

    const float* embp1 = emb + (size_t)gr1 * FEMB + kq;
    const float* embp2 = emb + (size_t)gr2 * FEMB + kq;
    const float* Wp    = W + (size_t)(col0 + wc0) * FTOT + wk;

    // ===================== main loop: pure embedding region =====================
    for (int f0 = 0; f0 < FEMB; f0 += BK) {
        float4 a1 = *(const float4*)(embp1 + f0);
        float4 a2 = *(const float4*)(embp2 + f0);

        float wv[8];
#pragma unroll
        for (int j = 0; j < 8; j++)
            wv[j] = Wp[(size_t)f0 + (size_t)j * 16 * FTOT];

        As[kq + 0][r1] = a1.x; As[kq + 1][r1] = a1.y;
        As[kq + 2][r1] = a1.z; As[kq + 3][r1] = a1.w;
        As[kq + 0][r2] = a2.x; As[kq + 1][r2] = a2.y;
        As[kq + 2][r2] = a2.z; As[kq + 3][r2] = a2.w;
#pragma unroll
        for (int j = 0; j < 8; j++)
            Ws[wk][wc0 + j * 16] = wv[j];

        __syncthreads();
#pragma unroll
        for (int k = 0; k < BK; k++) {
            float4 av0 = *(const float4*)&As[k][ty * 8];
            float4 av1 = *(const float4*)&As[k][ty * 8 + 4];
            float4 bv0 = *(const float4*)&Ws[k][tx * 8];
            float4 bv1 = *(const float4*)&Ws[k][tx * 8 + 4];
            float a[8] = {av0.x, av0.y, av0.z, av0.w, av1.x, av1.y, av1.z, av1.w};
            float w[8] = {bv0.x, bv0.y, bv0.z, bv0.w, bv1.x, bv1.y, bv1.z, bv1.w};
#pragma unroll
            for (int i = 0; i < 8; i++)
#pragma unroll
                for (int j = 0; j < 8; j++)
                    acc[i][j] = fmaf(a[i], w[j], acc[i][j]);
        }
        __syncthreads();
    }

    // ===================== tail: vis/bbox/kpts (61 features) =====================
    for (int f0 = FEMB; f0 < FTOT; f0 += BK) {
#pragma unroll
        for (int i = 0; i < 8; i++)
            As[k3 + i][r3] = load_feat(emb, vis, bb, kp, gr3, f0 + k3 + i);
#pragma unroll
        for (int j = 0; j < 8; j++) {
            int f = f0 + wk;
            Ws[wk][wc0 + j * 16] =
                (f < FTOT) ? W[(size_t)(col0 + wc0 + j * 16) * FTOT + f] : 0.f;
        }
        __syncthreads();
#pragma unroll
        for (int k = 0; k < BK; k++) {
            float4 av0 = *(const float4*)&As[k][ty * 8];
            float4 av1 = *(const float4*)&As[k][ty * 8 + 4];
            float4 bv0 = *(const float4*)&Ws[k][tx * 8];
            float4 bv1 = *(const float4*)&Ws[k][tx * 8 + 4];
            float a[8] = {av0.x, av0.y, av0.z, av0.w, av1.x, av1.y, av1.z, av1.w};
            float w[8] = {bv0.x, bv0.y, bv0.z, bv0.w, bv1.x, bv1.y, bv1.z, bv1.w};
#pragma unroll
            for (int i = 0; i < 8; i++)
#pragma unroll
                for (int j = 0; j < 8; j++)
                    acc[i][j] = fmaf(a[i], w[j], acc[i][j]);
        }
        __syncthreads();
    }

    // ===================== epilogue: bias + scatter =====================
    float4 bb0 = *(const float4*)(bias + col0 + tx * 8);
    float4 bb1 = *(const float4*)(bias + col0 + tx * 8 + 4);
#pragma unroll
    for (int i = 0; i < 8; i++) {
        int r = row0 + ty * 8 + i;
        if (r < cnt) {
            int g = g_rows[r];
            float* o = out + (size_t)g * TDIM + col0 + tx * 8;
            float4 v0 = make_float4(acc[i][0] + bb0.x, acc[i][1] + bb0.y,
                                    acc[i][2] + bb0.z, acc[i][3] + bb0.w);
            float4 v1 = make_float4(acc[i][4] + bb1.x, acc[i][5] + bb1.y,
                                    acc[i][6] + bb1.z, acc[i][7] + bb1.w);
            *(float4*)o       = v0;
            *(float4*)(o + 4) = v1;
        }
    }
}

// ---------------------------------------------------------------------------
extern "C" void kernel_launch(void* const* d_in, const int* in_sizes, int n_in,
                              void* d_out, int out_size) {
    const float* emb  = (const float*)d_in[0];
    const float* vis  = (const float*)d_in[1];
    const float* bb   = (const float*)d_in[2];
    const float* kp   = (const float*)d_in[3];
    const int*   mask = (const int*)d_in[4];    // jnp.bool_ -> int32 in harness
    const float* W    = (const float*)d_in[5];
    const float* bias = (const float*)d_in[6];
    float*       out  = (float*)d_out;

    int n4 = out_size / 4;  // 16384*256 floats -> float4 count
    zero_and_reset<<<2048, 256>>>((float4*)out, n4);
    compact_rows<<<MTOT / 256, 256>>>(mask);
    gemm_masked<<<dim3(MTOT / BM, TDIM / BN), 256>>>(emb, vis, bb, kp, W, bias, out);
}

// round 4
// speedup vs baseline: 3.2279x; 3.2279x over previous
#include <cuda_runtime.h>
#include <cuda_bf16.h>
#include <cstdint>

#define MTOT 16384
#define FEMB 3072
#define FVIS 6
#define FBB  4
#define FKP  51
#define FTOT 3133
#define TDIM 256
#define KPAD 3136          // 98 * 32
#define BM 128
#define BN 128
#define BK 32
#define NSTEP (KPAD / BK)  // 98
#define AT_B (BM * BK * 2) // one bf16 tile = 8192 B
#define STAGE_B (4 * AT_B) // Ah, Al, Wh, Wl
#define SMEM_TOTAL (2 * STAGE_B)  // 64 KB double-buffered

__device__ int g_count;
__device__ int g_rows[MTOT];
__device__ __align__(16) __nv_bfloat16 g_Whi[TDIM * KPAD];
__device__ __align__(16) __nv_bfloat16 g_Wlo[TDIM * KPAD];

// ---------------------------------------------------------------- helpers
__device__ __forceinline__ uint32_t smem_u32(const void* p) {
    uint32_t a;
    asm("{ .reg .u64 t; cvta.to.shared.u64 t, %1; cvt.u32.u64 %0, t; }"
        : "=r"(a) : "l"(p));
    return a;
}

#define LDSM4(r0, r1, r2, r3, addr)                                          \
    asm volatile("ldmatrix.sync.aligned.m8n8.x4.shared.b16 {%0,%1,%2,%3}, [%4];" \
        : "=r"(r0), "=r"(r1), "=r"(r2), "=r"(r3) : "r"(addr))

#define MMA(c, a0, a1, a2, a3, b0, b1)                                       \
    asm volatile("mma.sync.aligned.m16n8k16.row.col.f32.bf16.bf16.f32 "      \
        "{%0,%1,%2,%3},{%4,%5,%6,%7},{%8,%9},{%0,%1,%2,%3};"                 \
        : "+f"((c)[0]), "+f"((c)[1]), "+f"((c)[2]), "+f"((c)[3])             \
        : "r"(a0), "r"(a1), "r"(a2), "r"(a3), "r"(b0), "r"(b1))

__device__ __forceinline__ uint32_t bf2u(__nv_bfloat162 v) {
    return *reinterpret_cast<uint32_t*>(&v);
}

// hi/lo bf16 split of 8 floats into two uint4
__device__ __forceinline__ void split8(const float* v, uint4& H, uint4& L) {
    __nv_bfloat162 h0 = __floats2bfloat162_rn(v[0], v[1]);
    __nv_bfloat162 h1 = __floats2bfloat162_rn(v[2], v[3]);
    __nv_bfloat162 h2 = __floats2bfloat162_rn(v[4], v[5]);
    __nv_bfloat162 h3 = __floats2bfloat162_rn(v[6], v[7]);
    __nv_bfloat162 l0 = __floats2bfloat162_rn(v[0] - __bfloat162float(h0.x),
                                              v[1] - __bfloat162float(h0.y));
    __nv_bfloat162 l1 = __floats2bfloat162_rn(v[2] - __bfloat162float(h1.x),
                                              v[3] - __bfloat162float(h1.y));
    __nv_bfloat162 l2 = __floats2bfloat162_rn(v[4] - __bfloat162float(h2.x),
                                              v[5] - __bfloat162float(h2.y));
    __nv_bfloat162 l3 = __floats2bfloat162_rn(v[6] - __bfloat162float(h3.x),
                                              v[7] - __bfloat162float(h3.y));
    H = make_uint4(bf2u(h0), bf2u(h1), bf2u(h2), bf2u(h3));
    L = make_uint4(bf2u(l0), bf2u(l1), bf2u(l2), bf2u(l3));
}

__device__ __forceinline__ float tail_feat(
    const float* __restrict__ vis, const float* __restrict__ bb,
    const float* __restrict__ kp, int g, int f)
{
    int d = f - FEMB;
    if (d < FVIS)              return vis[(size_t)g * FVIS + d];
    if (d < FVIS + FBB)        return bb[(size_t)g * FBB + d - FVIS];
    if (d < FVIS + FBB + FKP)  return kp[(size_t)g * FKP + d - FVIS - FBB];
    return 0.f;
}

// ---------------------------------------------------------------------------
// Kernel 1: reset counter + pre-split W into padded bf16 hi/lo
// ---------------------------------------------------------------------------
__global__ void wsplit(const float* __restrict__ W) {
    if (blockIdx.x == 0 && threadIdx.x == 0) g_count = 0;
    int idx = blockIdx.x * blockDim.x + threadIdx.x;
    if (idx >= TDIM * KPAD) return;
    int n = idx / KPAD, f = idx - n * KPAD;
    float v = (f < FTOT) ? W[(size_t)n * FTOT + f] : 0.f;
    __nv_bfloat16 h = __float2bfloat16(v);
    g_Whi[idx] = h;
    g_Wlo[idx] = __float2bfloat16(v - __bfloat162float(h));
}

// ---------------------------------------------------------------------------
// Kernel 2: compact active rows + zero inactive output rows
// ---------------------------------------------------------------------------
__global__ void compact_zero(const int* __restrict__ mask, float4* __restrict__ out) {
    int m = blockIdx.x * blockDim.x + threadIdx.x;
    bool act = (mask[m] != 0);
    unsigned bal = __ballot_sync(0xFFFFFFFFu, act);
    int lane = threadIdx.x & 31;
    int base = 0;
    if (lane == 0 && bal) base = atomicAdd(&g_count, __popc(bal));
    base = __shfl_sync(0xFFFFFFFFu, base, 0);
    if (act) {
        g_rows[base + __popc(bal & ((1u << lane) - 1u))] = m;
    } else {
        float4* o = out + (size_t)m * (TDIM / 4);
        float4 z = make_float4(0.f, 0.f, 0.f, 0.f);
#pragma unroll
        for (int i = 0; i < TDIM / 4; i++) o[i] = z;
    }
}

// ---------------------------------------------------------------------------
// Kernel 3: bf16-split GEMM via mma.sync (generic PTX tensor cores).
// C[g, t] = sum_f A[g,f] * W[t,f] + b[t] over compacted rows.
// ---------------------------------------------------------------------------
__global__ __launch_bounds__(256) void gemm_mma(
    const float* __restrict__ emb, const float* __restrict__ vis,
    const float* __restrict__ bb,  const float* __restrict__ kp,
    const float* __restrict__ bias, float* __restrict__ out)
{
    extern __shared__ char smem[];
    const int cnt = g_count;
    const int row0 = blockIdx.x * BM;
    if (row0 >= cnt) return;
    const int col0 = blockIdx.y * BN;

    const int tid = threadIdx.x;
    const int lane = tid & 31;
    const int wid = tid >> 5;
    const int wm = wid >> 2;      // 0..1  (64-row half)
    const int wn = wid & 3;       // 0..3  (32-col quarter)

    const uint32_t sbase = smem_u32(smem);

    // ---- loader mapping: thread -> (tile row, 16-feature half) ----
    const int lr = tid >> 1;
    const int lh = (tid & 1) * 16;
    const int ga = g_rows[min(row0 + lr, cnt - 1)];
    const float* arow = emb + (size_t)ga * FEMB;
    const __nv_bfloat16* whrow = g_Whi + (size_t)(col0 + lr) * KPAD;
    const __nv_bfloat16* wlrow = g_Wlo + (size_t)(col0 + lr) * KPAD;

    // swizzled 16B-chunk store offsets: row stride 64B, chunk = k>>3,
    // swizzle chunk ^= (row & 3)
    const uint32_t c0i = (uint32_t)(lh >> 3);
    const uint32_t sts0 = lr * 64 + (((c0i)     ^ (lr & 3)) << 4);
    const uint32_t sts1 = lr * 64 + (((c0i + 1) ^ (lr & 3)) << 4);

    // ---- ldmatrix per-thread addressing components ----
    const uint32_t lane4 = (uint32_t)(lane & 3);
    const uint32_t aRow  = (uint32_t)(wm * 64 + (lane & 15));
    const uint32_t aSel  = (uint32_t)(lane >> 4);          // 0/1 -> k-chunk
    const uint32_t bRow  = (uint32_t)(wn * 32 + (lane & 7) + ((lane >> 4) << 3));
    const uint32_t bSel  = (uint32_t)((lane >> 3) & 1);

    float acc[4][4][4];
#pragma unroll
    for (int i = 0; i < 4; i++)
#pragma unroll
        for (int j = 0; j < 4; j++)
#pragma unroll
            for (int q = 0; q < 4; q++) acc[i][j][q] = 0.f;

    float a[16];
    uint4 WH0, WH1, WL0, WL1;

    auto prefetch = [&](int s) {
        const int f = s * BK + lh;
        if (f < FEMB) {
            const float4* p = (const float4*)(arow + f);
            *(float4*)(a + 0)  = p[0];
            *(float4*)(a + 4)  = p[1];
            *(float4*)(a + 8)  = p[2];
            *(float4*)(a + 12) = p[3];
        } else {
#pragma unroll
            for (int e = 0; e < 16; e++) a[e] = tail_feat(vis, bb, kp, ga, f + e);
        }
        WH0 = *(const uint4*)(whrow + f);
        WH1 = *(const uint4*)(whrow + f + 8);
        WL0 = *(const uint4*)(wlrow + f);
        WL1 = *(const uint4*)(wlrow + f + 8);
    };

    prefetch(0);

    for (int s = 0; s < NSTEP; ++s) {
        char* buf = smem + (s & 1) * STAGE_B;

        // ---- convert + store this stage's tiles ----
        uint4 H0, L0, H1, L1;
        split8(a,     H0, L0);
        split8(a + 8, H1, L1);
        *(uint4*)(buf + sts0)            = H0;   // Ah
        *(uint4*)(buf + sts1)            = H1;
        *(uint4*)(buf + AT_B + sts0)     = L0;   // Al
        *(uint4*)(buf + AT_B + sts1)     = L1;
        *(uint4*)(buf + 2 * AT_B + sts0) = WH0;  // Wh
        *(uint4*)(buf + 2 * AT_B + sts1) = WH1;
        *(uint4*)(buf + 3 * AT_B + sts0) = WL0;  // Wl
        *(uint4*)(buf + 3 * AT_B + sts1) = WL1;

        __syncthreads();

        if (s + 1 < NSTEP) prefetch(s + 1);      // LDG in flight during mma

        const uint32_t pAh = sbase + (s & 1) * STAGE_B;
        const uint32_t pWh = pAh + 2 * AT_B;
        const uint32_t pWl = pAh + 3 * AT_B;

#pragma unroll
        for (int kk = 0; kk < 2; kk++) {
            const uint32_t cA = ((uint32_t)(kk * 2) + aSel) ^ lane4;
            const uint32_t cB = ((uint32_t)(kk * 2) + bSel) ^ lane4;

            uint32_t bh[8], bl[8];
            const uint32_t aB0 = bRow * 64 + (cB << 4);
            LDSM4(bh[0], bh[1], bh[2], bh[3], pWh + aB0);
            LDSM4(bh[4], bh[5], bh[6], bh[7], pWh + aB0 + 16 * 64);
            LDSM4(bl[0], bl[1], bl[2], bl[3], pWl + aB0);
            LDSM4(bl[4], bl[5], bl[6], bl[7], pWl + aB0 + 16 * 64);

#pragma unroll
            for (int mt = 0; mt < 4; mt++) {
                const uint32_t aA = (aRow + mt * 16) * 64 + (cA << 4);
                uint32_t ah0, ah1, ah2, ah3, al0, al1, al2, al3;
                LDSM4(ah0, ah1, ah2, ah3, pAh + aA);
                LDSM4(al0, al1, al2, al3, pAh + AT_B + aA);
#pragma unroll
                for (int nt = 0; nt < 4; nt++) {
                    MMA(acc[mt][nt], ah0, ah1, ah2, ah3, bh[2 * nt], bh[2 * nt + 1]);
                    MMA(acc[mt][nt], ah0, ah1, ah2, ah3, bl[2 * nt], bl[2 * nt + 1]);
                    MMA(acc[mt][nt], al0, al1, al2, al3, bh[2 * nt], bh[2 * nt + 1]);
                }
            }
        }
        // one sync per stage is sufficient with double buffering
    }

    // ---------------- epilogue: bias + scatter ----------------
#pragma unroll
    for (int mt = 0; mt < 4; mt++) {
        const int mlo = wm * 64 + mt * 16 + (lane >> 2);
        const int r1 = row0 + mlo;
        const int r2 = r1 + 8;
#pragma unroll
        for (int nt = 0; nt < 4; nt++) {
            const int c = col0 + wn * 32 + nt * 8 + (lane & 3) * 2;
            const float2 bv = *(const float2*)(bias + c);
            if (r1 < cnt) {
                const int g = g_rows[r1];
                float2 o = make_float2(acc[mt][nt][0] + bv.x, acc[mt][nt][1] + bv.y);
                *(float2*)(out + (size_t)g * TDIM + c) = o;
            }
            if (r2 < cnt) {
                const int g = g_rows[r2];
                float2 o = make_float2(acc[mt][nt][2] + bv.x, acc[mt][nt][3] + bv.y);
                *(float2*)(out + (size_t)g * TDIM + c) = o;
            }
        }
    }
}

// ---------------------------------------------------------------------------
extern "C" void kernel_launch(void* const* d_in, const int* in_sizes, int n_in,
                              void* d_out, int out_size) {
    const float* emb  = (const float*)d_in[0];
    const float* vis  = (const float*)d_in[1];
    const float* bb   = (const float*)d_in[2];
    const float* kp   = (const float*)d_in[3];
    const int*   mask = (const int*)d_in[4];
    const float* W    = (const float*)d_in[5];
    const float* bias = (const float*)d_in[6];
    float*       out  = (float*)d_out;

    static bool configured = false;
    if (!configured) {
        cudaFuncSetAttribute(gemm_mma, cudaFuncAttributeMaxDynamicSharedMemorySize,
                             SMEM_TOTAL);
        configured = true;
    }

    wsplit<<<(TDIM * KPAD + 255) / 256, 256>>>(W);
    compact_zero<<<MTOT / 256, 256>>>(mask, (float4*)out);
    gemm_mma<<<dim3(MTOT / BM, TDIM / BN), 256, SMEM_TOTAL>>>(
        emb, vis, bb, kp, bias, out);
}

// round 5
// speedup vs baseline: 4.9519x; 1.5341x over previous
#include <cuda_runtime.h>
#include <cuda_fp16.h>
#include <cstdint>

#define MTOT 16384
#define FEMB 3072
#define FVIS 6
#define FBB  4
#define FKP  51
#define FTOT 3133
#define TDIM 256
#define KPAD 3136          // 98 * 32
#define BM 128
#define BN 128
#define BK 32
#define NSTEP (KPAD / BK)  // 98
#define AT_B (BM * BK * 2) // one fp16 tile = 8192 B
#define WPAIR_B (2 * AT_B) // Wh + Wl = 16384 B
#define SMEM_TOTAL (2 * AT_B + 4 * WPAIR_B)  // A double + W quad = 80 KB

__device__ int g_count;
__device__ int g_rows[MTOT];
__device__ __align__(16) __half g_Whi[TDIM * KPAD];
__device__ __align__(16) __half g_Wlo[TDIM * KPAD];

// ---------------------------------------------------------------- helpers
__device__ __forceinline__ uint32_t smem_u32(const void* p) {
    uint32_t a;
    asm("{ .reg .u64 t; cvta.to.shared.u64 t, %1; cvt.u32.u64 %0, t; }"
        : "=r"(a) : "l"(p));
    return a;
}

#define LDSM4(r0, r1, r2, r3, addr)                                          \
    asm volatile("ldmatrix.sync.aligned.m8n8.x4.shared.b16 {%0,%1,%2,%3}, [%4];" \
        : "=r"(r0), "=r"(r1), "=r"(r2), "=r"(r3) : "r"(addr))

#define MMA(c, a0, a1, a2, a3, b0, b1)                                       \
    asm volatile("mma.sync.aligned.m16n8k16.row.col.f32.f16.f16.f32 "        \
        "{%0,%1,%2,%3},{%4,%5,%6,%7},{%8,%9},{%0,%1,%2,%3};"                 \
        : "+f"((c)[0]), "+f"((c)[1]), "+f"((c)[2]), "+f"((c)[3])             \
        : "r"(a0), "r"(a1), "r"(a2), "r"(a3), "r"(b0), "r"(b1))

#define CP_ASYNC16(dst, src)                                                 \
    asm volatile("cp.async.cg.shared.global [%0], [%1], 16;"                 \
        :: "r"(dst), "l"(src) : "memory")
#define CP_COMMIT() asm volatile("cp.async.commit_group;" ::: "memory")
#define CP_WAIT2()  asm volatile("cp.async.wait_group 2;" ::: "memory")

__device__ __forceinline__ uint32_t h2u(__half2 v) {
    return *reinterpret_cast<uint32_t*>(&v);
}

// pack 8 floats -> 8 fp16 (one uint4)
__device__ __forceinline__ void pack8(const float* v, uint4& H) {
    __half2 h0 = __float22half2_rn(make_float2(v[0], v[1]));
    __half2 h1 = __float22half2_rn(make_float2(v[2], v[3]));
    __half2 h2 = __float22half2_rn(make_float2(v[4], v[5]));
    __half2 h3 = __float22half2_rn(make_float2(v[6], v[7]));
    H = make_uint4(h2u(h0), h2u(h1), h2u(h2), h2u(h3));
}

__device__ __forceinline__ float tail_feat(
    const float* __restrict__ vis, const float* __restrict__ bb,
    const float* __restrict__ kp, int g, int f)
{
    int d = f - FEMB;
    if (d < FVIS)              return vis[(size_t)g * FVIS + d];
    if (d < FVIS + FBB)        return bb[(size_t)g * FBB + d - FVIS];
    if (d < FVIS + FBB + FKP)  return kp[(size_t)g * FKP + d - FVIS - FBB];
    return 0.f;
}

// ---------------------------------------------------------------------------
// Kernel 1: reset counter + pre-split W into padded fp16 hi/lo
// ---------------------------------------------------------------------------
__global__ void wsplit(const float* __restrict__ W) {
    if (blockIdx.x == 0 && threadIdx.x == 0) g_count = 0;
    int idx = blockIdx.x * blockDim.x + threadIdx.x;
    if (idx >= TDIM * KPAD) return;
    int n = idx / KPAD, f = idx - n * KPAD;
    float v = (f < FTOT) ? W[(size_t)n * FTOT + f] : 0.f;
    __half h = __float2half_rn(v);
    g_Whi[idx] = h;
    g_Wlo[idx] = __float2half_rn(v - __half2float(h));
}

// ---------------------------------------------------------------------------
// Kernel 2: compact active rows + zero inactive output rows
// ---------------------------------------------------------------------------
__global__ void compact_zero(const int* __restrict__ mask, float4* __restrict__ out) {
    int m = blockIdx.x * blockDim.x + threadIdx.x;
    bool act = (mask[m] != 0);
    unsigned bal = __ballot_sync(0xFFFFFFFFu, act);
    int lane = threadIdx.x & 31;
    int base = 0;
    if (lane == 0 && bal) base = atomicAdd(&g_count, __popc(bal));
    base = __shfl_sync(0xFFFFFFFFu, base, 0);
    if (act) {
        g_rows[base + __popc(bal & ((1u << lane) - 1u))] = m;
    } else {
        float4* o = out + (size_t)m * (TDIM / 4);
        float4 z = make_float4(0.f, 0.f, 0.f, 0.f);
#pragma unroll
        for (int i = 0; i < TDIM / 4; i++) o[i] = z;
    }
}

// ---------------------------------------------------------------------------
// Kernel 3: fp16 GEMM, A single-precision-split-free, W = Wh + Wl (2 MMAs).
// C[g, t] = sum_f A[g,f] * (Wh+Wl)[t,f] + b[t] over compacted rows.
// ---------------------------------------------------------------------------
__global__ __launch_bounds__(256) void gemm_mma(
    const float* __restrict__ emb, const float* __restrict__ vis,
    const float* __restrict__ bb,  const float* __restrict__ kp,
    const float* __restrict__ bias, float* __restrict__ out)
{
    extern __shared__ char smem[];
    const int cnt = g_count;
    const int row0 = blockIdx.x * BM;
    if (row0 >= cnt) return;
    const int col0 = blockIdx.y * BN;

    const int tid = threadIdx.x;
    const int lane = tid & 31;
    const int wid = tid >> 5;
    const int wm = wid >> 2;      // 0..1  (64-row half)
    const int wn = wid & 3;       // 0..3  (32-col quarter)

    const uint32_t sbase = smem_u32(smem);
    const uint32_t sW = sbase + 2 * AT_B;     // 4 W pairs follow the A buffers

    // ---- loader mapping: thread -> (tile row, 16-feature half) ----
    const int lr = tid >> 1;
    const int lh = (tid & 1) * 16;
    const int ga = g_rows[min(row0 + lr, cnt - 1)];
    const float* arow = emb + (size_t)ga * FEMB;
    const __half* whrow = g_Whi + (size_t)(col0 + lr) * KPAD;
    const __half* wlrow = g_Wlo + (size_t)(col0 + lr) * KPAD;

    // swizzled 16B-chunk store offsets: row stride 64B, chunk ^= (row & 3)
    const uint32_t c0i = (uint32_t)(lh >> 3);
    const uint32_t swz0 = ((c0i)     ^ (uint32_t)(lr & 3)) << 4;
    const uint32_t swz1 = ((c0i + 1) ^ (uint32_t)(lr & 3)) << 4;
    const uint32_t sts0 = (uint32_t)lr * 64 + swz0;
    const uint32_t sts1 = (uint32_t)lr * 64 + swz1;

    // ---- ldmatrix per-thread addressing ----
    const uint32_t lane4 = (uint32_t)(lane & 3);
    const uint32_t aRow  = (uint32_t)(wm * 64 + (lane & 15));
    const uint32_t aSel  = (uint32_t)(lane >> 4);
    const uint32_t bRow  = (uint32_t)(wn * 32 + (lane & 7) + ((lane >> 4) << 3));
    const uint32_t bSel  = (uint32_t)((lane >> 3) & 1);

    float acc[4][4][4];
#pragma unroll
    for (int i = 0; i < 4; i++)
#pragma unroll
        for (int j = 0; j < 4; j++)
#pragma unroll
            for (int q = 0; q < 4; q++) acc[i][j][q] = 0.f;

    float a[16];

    auto prefetchA = [&](int s) {
        const int f = s * BK + lh;
        if (f < FEMB) {
            const float4* p = (const float4*)(arow + f);
            *(float4*)(a + 0)  = p[0];
            *(float4*)(a + 4)  = p[1];
            *(float4*)(a + 8)  = p[2];
            *(float4*)(a + 12) = p[3];
        } else {
#pragma unroll
            for (int e = 0; e < 16; e++) a[e] = tail_feat(vis, bb, kp, ga, f + e);
        }
    };

    auto issueW = [&](int s) {
        if (s < NSTEP) {
            uint32_t base = sW + (uint32_t)(s & 3) * WPAIR_B + (uint32_t)lr * 64;
            const __half* sh = whrow + s * BK + lh;
            const __half* sl = wlrow + s * BK + lh;
            CP_ASYNC16(base + swz0, sh);
            CP_ASYNC16(base + swz1, sh + 8);
            CP_ASYNC16(base + AT_B + swz0, sl);
            CP_ASYNC16(base + AT_B + swz1, sl + 8);
        }
        CP_COMMIT();
    };

    issueW(0);
    issueW(1);
    prefetchA(0);

    for (int s = 0; s < NSTEP; ++s) {
        const uint32_t ab = (uint32_t)(s & 1) * AT_B;
        char* abuf = smem + ab;

        // ---- convert + store this stage's A tile ----
        uint4 H0, H1;
        pack8(a,     H0);
        pack8(a + 8, H1);
        *(uint4*)(abuf + sts0) = H0;
        *(uint4*)(abuf + sts1) = H1;

        issueW(s + 2);
        CP_WAIT2();              // W(s) landed (per-thread)
        __syncthreads();         // publish A(s) stores + everyone's W(s)

        if (s + 1 < NSTEP) prefetchA(s + 1);   // LDG in flight behind MMAs

        const uint32_t pA  = sbase + ab;
        const uint32_t pWh = sW + (uint32_t)(s & 3) * WPAIR_B;
        const uint32_t pWl = pWh + AT_B;

#pragma unroll
        for (int kk = 0; kk < 2; kk++) {
            const uint32_t cA = ((uint32_t)(kk * 2) + aSel) ^ lane4;
            const uint32_t cB = ((uint32_t)(kk * 2) + bSel) ^ lane4;

            uint32_t bh[8], bl[8];
            const uint32_t aB0 = bRow * 64 + (cB << 4);
            LDSM4(bh[0], bh[1], bh[2], bh[3], pWh + aB0);
            LDSM4(bh[4], bh[5], bh[6], bh[7], pWh + aB0 + 16 * 64);
            LDSM4(bl[0], bl[1], bl[2], bl[3], pWl + aB0);
            LDSM4(bl[4], bl[5], bl[6], bl[7], pWl + aB0 + 16 * 64);

#pragma unroll
            for (int mt = 0; mt < 4; mt++) {
                const uint32_t aA = (aRow + mt * 16) * 64 + (cA << 4);
                uint32_t a0, a1, a2, a3;
                LDSM4(a0, a1, a2, a3, pA + aA);
#pragma unroll
                for (int nt = 0; nt < 4; nt++) {
                    MMA(acc[mt][nt], a0, a1, a2, a3, bh[2 * nt], bh[2 * nt + 1]);
                    MMA(acc[mt][nt], a0, a1, a2, a3, bl[2 * nt], bl[2 * nt + 1]);
                }
            }
        }
    }

    // ---------------- epilogue: bias + scatter ----------------
#pragma unroll
    for (int mt = 0; mt < 4; mt++) {
        const int mlo = wm * 64 + mt * 16 + (lane >> 2);
        const int r1 = row0 + mlo;
        const int r2 = r1 + 8;
#pragma unroll
        for (int nt = 0; nt < 4; nt++) {
            const int c = col0 + wn * 32 + nt * 8 + (lane & 3) * 2;
            const float2 bv = *(const float2*)(bias + c);
            if (r1 < cnt) {
                const int g = g_rows[r1];
                float2 o = make_float2(acc[mt][nt][0] + bv.x, acc[mt][nt][1] + bv.y);
                *(float2*)(out + (size_t)g * TDIM + c) = o;
            }
            if (r2 < cnt) {
                const int g = g_rows[r2];
                float2 o = make_float2(acc[mt][nt][2] + bv.x, acc[mt][nt][3] + bv.y);
                *(float2*)(out + (size_t)g * TDIM + c) = o;
            }
        }
    }
}

// ---------------------------------------------------------------------------
extern "C" void kernel_launch(void* const* d_in, const int* in_sizes, int n_in,
                              void* d_out, int out_size) {
    const float* emb  = (const float*)d_in[0];
    const float* vis  = (const float*)d_in[1];
    const float* bb   = (const float*)d_in[2];
    const float* kp   = (const float*)d_in[3];
    const int*   mask = (const int*)d_in[4];
    const float* W    = (const float*)d_in[5];
    const float* bias = (const float*)d_in[6];
    float*       out  = (float*)d_out;

    static bool configured = false;
    if (!configured) {
        cudaFuncSetAttribute(gemm_mma, cudaFuncAttributeMaxDynamicSharedMemorySize,
                             SMEM_TOTAL);
        configured = true;
    }

    wsplit<<<(TDIM * KPAD + 255) / 256, 256>>>(W);
    compact_zero<<<MTOT / 256, 256>>>(mask, (float4*)out);
    gemm_mma<<<dim3(MTOT / BM, TDIM / BN), 256, SMEM_TOTAL>>>(
        emb, vis, bb, kp, bias, out);
}